// round 10
// baseline (speedup 1.0000x reference)
#include <cuda_runtime.h>
#include <cuda_bf16.h>

#define N_NODES 50000
#define N_EDGES 800000
#define F_IN    512
#define F_HID   256
#define F_OUT   128

#define SCAN_BLOCKS 64           // 64 * 1024 >= N_NODES

// Scratch
__device__ float g_H0[(size_t)N_NODES * F_HID];
__device__ float g_H1[(size_t)N_NODES * F_HID];
__device__ float g_H2[(size_t)N_NODES * F_OUT];
__device__ int   g_deg[N_NODES];
__device__ int   g_part[N_NODES];
__device__ int   g_bsum[SCAN_BLOCKS];
__device__ int   g_offsets[N_NODES + 1];
__device__ int   g_cursor[N_NODES];
__device__ int   g_ssrc[N_EDGES];
__device__ float g_sw[N_EDGES];

// ---------------------------------------------------------------------------
// CSR build kernels
// ---------------------------------------------------------------------------
__global__ void zero_deg_kernel() {
    int i = blockIdx.x * blockDim.x + threadIdx.x;
    if (i < N_NODES) g_deg[i] = 0;
}

__global__ void hist_kernel(const int* __restrict__ dst) {
    int e = blockIdx.x * blockDim.x + threadIdx.x;
    if (e < N_EDGES) atomicAdd(&g_deg[dst[e]], 1);
}

__global__ __launch_bounds__(1024)
void scan_blocks_kernel() {
    __shared__ int sm[1024];
    int tid = threadIdx.x;
    int i = blockIdx.x * 1024 + tid;
    int v = (i < N_NODES) ? g_deg[i] : 0;
    sm[tid] = v;
    __syncthreads();
    #pragma unroll
    for (int d = 1; d < 1024; d <<= 1) {
        int t = (tid >= d) ? sm[tid - d] : 0;
        __syncthreads();
        sm[tid] += t;
        __syncthreads();
    }
    if (i < N_NODES) g_part[i] = sm[tid] - v;       // exclusive within block
    if (tid == 1023) g_bsum[blockIdx.x] = sm[1023]; // block total
}

__global__ void scan_sums_kernel() {   // 1 block, SCAN_BLOCKS threads
    __shared__ int sm[SCAN_BLOCKS];
    int tid = threadIdx.x;
    int v = g_bsum[tid];
    sm[tid] = v;
    __syncthreads();
    #pragma unroll
    for (int d = 1; d < SCAN_BLOCKS; d <<= 1) {
        int t = (tid >= d) ? sm[tid - d] : 0;
        __syncthreads();
        sm[tid] += t;
        __syncthreads();
    }
    g_bsum[tid] = sm[tid] - v;         // exclusive
}

__global__ void add_off_kernel() {
    int i = blockIdx.x * blockDim.x + threadIdx.x;
    if (i < N_NODES) {
        int off = g_part[i] + g_bsum[i >> 10];
        g_offsets[i] = off;
        g_cursor[i]  = off;
    }
    if (i == 0) g_offsets[N_NODES] = N_EDGES;
}

__global__ void fill_kernel(const int* __restrict__ src,
                            const int* __restrict__ dst,
                            const float* __restrict__ w) {
    int e = blockIdx.x * blockDim.x + threadIdx.x;
    if (e >= N_EDGES) return;
    int d = dst[e];
    int pos = atomicAdd(&g_cursor[d], 1);
    g_ssrc[pos] = src[e];
    g_sw[pos]   = w[e];
}

// ---------------------------------------------------------------------------
// CSR SpMM: warp per node, register accumulation, one coalesced store.
// ---------------------------------------------------------------------------
template<int F>
__global__ __launch_bounds__(256)
void spmm_csr_kernel(const float* __restrict__ x, float* __restrict__ y) {
    int node = (blockIdx.x * 256 + threadIdx.x) >> 5;
    if (node >= N_NODES) return;
    int lane = threadIdx.x & 31;

    int beg = g_offsets[node];
    int end = g_offsets[node + 1];

    float4 acc0 = make_float4(0.f, 0.f, 0.f, 0.f);
    float4 acc1 = make_float4(0.f, 0.f, 0.f, 0.f);   // used only if F==256

    for (int j = beg; j < end; j++) {
        int s    = __ldg(&g_ssrc[j]);
        float wv = __ldg(&g_sw[j]);
        const float4* xr = (const float4*)(x + (size_t)s * F);
        float4 v0 = __ldg(&xr[lane]);
        acc0.x = fmaf(wv, v0.x, acc0.x);
        acc0.y = fmaf(wv, v0.y, acc0.y);
        acc0.z = fmaf(wv, v0.z, acc0.z);
        acc0.w = fmaf(wv, v0.w, acc0.w);
        if (F == 256) {
            float4 v1 = __ldg(&xr[lane + 32]);
            acc1.x = fmaf(wv, v1.x, acc1.x);
            acc1.y = fmaf(wv, v1.y, acc1.y);
            acc1.z = fmaf(wv, v1.z, acc1.z);
            acc1.w = fmaf(wv, v1.w, acc1.w);
        }
    }

    float4* yr = (float4*)(y + (size_t)node * F);
    yr[lane] = acc0;
    if (F == 256) yr[lane + 32] = acc1;
}

// ---------------------------------------------------------------------------
// GEMM helpers (3xBF16 split)
// ---------------------------------------------------------------------------
__device__ __forceinline__ void split_bf16x2(float f0, float f1,
                                             unsigned& hi, unsigned& lo) {
    asm("cvt.rn.bf16x2.f32 %0, %1, %2;" : "=r"(hi) : "f"(f1), "f"(f0));
    float fh0 = __uint_as_float(hi << 16);
    float fh1 = __uint_as_float(hi & 0xFFFF0000u);
    asm("cvt.rn.bf16x2.f32 %0, %1, %2;" : "=r"(lo)
        : "f"(f1 - fh1), "f"(f0 - fh0));
}

__device__ __forceinline__ void mma_bf16(float c[4], const unsigned a[4],
                                         const unsigned b[2]) {
    asm volatile(
        "mma.sync.aligned.m16n8k16.row.col.f32.bf16.bf16.f32 "
        "{%0,%1,%2,%3}, {%4,%5,%6,%7}, {%8,%9}, {%0,%1,%2,%3};"
        : "+f"(c[0]), "+f"(c[1]), "+f"(c[2]), "+f"(c[3])
        : "r"(a[0]), "r"(a[1]), "r"(a[2]), "r"(a[3]), "r"(b[0]), "r"(b[1]));
}

template<bool RELU_A>
__global__ __launch_bounds__(256, 2)
void gemm_tc_kernel(const float* __restrict__ A, const float* __restrict__ B,
                    float* __restrict__ C, int M, int N, int K) {
    constexpr int BM = 128, BK = 16;
    constexpr int AP = 12;
    constexpr int BP = 136;
    __shared__ __align__(16) unsigned As_hi[2][BM * AP];
    __shared__ __align__(16) unsigned As_lo[2][BM * AP];
    __shared__ __align__(16) unsigned Bs_hi[2][8 * BP];
    __shared__ __align__(16) unsigned Bs_lo[2][8 * BP];

    const int tid  = threadIdx.x;
    const int lane = tid & 31;
    const int warp = tid >> 5;
    const int g    = lane >> 2;
    const int tig  = lane & 3;
    const int warp_m = warp & 1;
    const int warp_n = warp >> 1;

    const int row0 = blockIdx.y * BM;
    const int col0 = blockIdx.x * 128;

    const int a_m0 = tid >> 2;
    const int a_kq = tid & 3;
    const int b_kp = tid >> 5;
    const int b_cq = (tid & 31) * 4;

    float acc[4][4][4];
    #pragma unroll
    for (int i = 0; i < 4; i++)
        #pragma unroll
        for (int j = 0; j < 4; j++)
            #pragma unroll
            for (int l = 0; l < 4; l++) acc[i][j][l] = 0.f;

    float4 a_reg[2], b_reg[2];

    auto ldg_tile = [&](int k0) {
        #pragma unroll
        for (int p = 0; p < 2; p++) {
            int m = a_m0 + p * 64;
            int gr = row0 + m;
            if (gr < M)
                a_reg[p] = *(const float4*)(A + (size_t)gr * K + k0 + a_kq * 4);
            else
                a_reg[p] = make_float4(0.f, 0.f, 0.f, 0.f);
        }
        b_reg[0] = *(const float4*)(B + (size_t)(k0 + 2 * b_kp)     * N + col0 + b_cq);
        b_reg[1] = *(const float4*)(B + (size_t)(k0 + 2 * b_kp + 1) * N + col0 + b_cq);
    };

    auto sts_tile = [&](int s) {
        #pragma unroll
        for (int p = 0; p < 2; p++) {
            int m = a_m0 + p * 64;
            float4 v = a_reg[p];
            if (RELU_A) {
                v.x = fmaxf(v.x, 0.f); v.y = fmaxf(v.y, 0.f);
                v.z = fmaxf(v.z, 0.f); v.w = fmaxf(v.w, 0.f);
            }
            unsigned h0, l0, h1, l1;
            split_bf16x2(v.x, v.y, h0, l0);
            split_bf16x2(v.z, v.w, h1, l1);
            int off = m * AP + a_kq * 2;
            *(uint2*)&As_hi[s][off] = make_uint2(h0, h1);
            *(uint2*)&As_lo[s][off] = make_uint2(l0, l1);
        }
        {
            unsigned h[4], l[4];
            split_bf16x2(b_reg[0].x, b_reg[1].x, h[0], l[0]);
            split_bf16x2(b_reg[0].y, b_reg[1].y, h[1], l[1]);
            split_bf16x2(b_reg[0].z, b_reg[1].z, h[2], l[2]);
            split_bf16x2(b_reg[0].w, b_reg[1].w, h[3], l[3]);
            int off = b_kp * BP + b_cq;
            *(uint4*)&Bs_hi[s][off] = make_uint4(h[0], h[1], h[2], h[3]);
            *(uint4*)&Bs_lo[s][off] = make_uint4(l[0], l[1], l[2], l[3]);
        }
    };

    // One pass = 16 independent MMAs (distinct accumulators). Same-acc reuse
    // across passes is separated by 16 MMAs -> no tensor dependency stalls.
    auto mma_pass = [&](const unsigned* As_p, const unsigned* Bs_p) {
        unsigned b[4][2];
        #pragma unroll
        for (int nt = 0; nt < 4; nt++) {
            int cb = warp_n * 32 + nt * 8 + g;
            b[nt][0] = Bs_p[tig * BP + cb];
            b[nt][1] = Bs_p[(tig + 4) * BP + cb];
        }
        #pragma unroll
        for (int mt = 0; mt < 4; mt++) {
            int rb = warp_m * 64 + mt * 16 + g;
            unsigned a[4];
            a[0] = As_p[rb * AP + tig];
            a[1] = As_p[(rb + 8) * AP + tig];
            a[2] = As_p[rb * AP + tig + 4];
            a[3] = As_p[(rb + 8) * AP + tig + 4];
            #pragma unroll
            for (int nt = 0; nt < 4; nt++)
                mma_bf16(acc[mt][nt], a, b[nt]);
        }
    };

    auto compute = [&](int s) {
        mma_pass(As_lo[s], Bs_hi[s]);   // a_lo * b_hi
        mma_pass(As_hi[s], Bs_lo[s]);   // a_hi * b_lo
        mma_pass(As_hi[s], Bs_hi[s]);   // a_hi * b_hi
    };

    const int T = K / BK;
    ldg_tile(0);
    for (int t = 0; t < T; t++) {
        sts_tile(t & 1);
        __syncthreads();
        if (t + 1 < T) ldg_tile((t + 1) * BK);
        compute(t & 1);
    }

    #pragma unroll
    for (int mt = 0; mt < 4; mt++) {
        int r_lo = row0 + warp_m * 64 + mt * 16 + g;
        int r_hi = r_lo + 8;
        #pragma unroll
        for (int nt = 0; nt < 4; nt++) {
            int c = col0 + warp_n * 32 + nt * 8 + 2 * tig;
            if (r_lo < M)
                *(float2*)(C + (size_t)r_lo * N + c) =
                    make_float2(acc[mt][nt][0], acc[mt][nt][1]);
            if (r_hi < M)
                *(float2*)(C + (size_t)r_hi * N + c) =
                    make_float2(acc[mt][nt][2], acc[mt][nt][3]);
        }
    }
}

// ---------------------------------------------------------------------------
// Launch
// ---------------------------------------------------------------------------
extern "C" void kernel_launch(void* const* d_in, const int* in_sizes, int n_in,
                              void* d_out, int out_size) {
    const float* X    = (const float*)d_in[0];
    const int*   esrc = (const int*)  d_in[1];
    const int*   edst = (const int*)  d_in[2];
    const float* ew   = (const float*)d_in[3];
    const float* W1   = (const float*)d_in[4];
    const float* W2   = (const float*)d_in[5];
    float* out = (float*)d_out;

    float *H0, *H1, *H2;
    cudaGetSymbolAddress((void**)&H0, g_H0);
    cudaGetSymbolAddress((void**)&H1, g_H1);
    cudaGetSymbolAddress((void**)&H2, g_H2);

    const int T = 256;
    const int MB = (N_NODES + 127) / 128;
    const int node_blocks = (N_NODES + T - 1) / T;
    const int edge_blocks = (N_EDGES + T - 1) / T;
    const int spmm_blocks = (N_NODES * 32 + T - 1) / T;   // warp per node

    // ---- CSR build (graph shared by both layers)
    zero_deg_kernel<<<node_blocks, T>>>();
    hist_kernel<<<edge_blocks, T>>>(edst);
    scan_blocks_kernel<<<SCAN_BLOCKS, 1024>>>();
    scan_sums_kernel<<<1, SCAN_BLOCKS>>>();
    add_off_kernel<<<node_blocks, T>>>();
    fill_kernel<<<edge_blocks, T>>>(esrc, edst, ew);

    // ---- layer 1
    gemm_tc_kernel<false><<<dim3(F_HID / 128, MB), T>>>(X, W1, H0,
                                                        N_NODES, F_HID, F_IN);
    spmm_csr_kernel<F_HID><<<spmm_blocks, T>>>(H0, H1);

    // ---- layer 2
    gemm_tc_kernel<true><<<dim3(F_OUT / 128, MB), T>>>(H1, W2, H2,
                                                       N_NODES, F_OUT, F_HID);
    spmm_csr_kernel<F_OUT><<<spmm_blocks, T>>>(H2, out);
}